// round 11
// baseline (speedup 1.0000x reference)
#include <cuda_runtime.h>

// FlowNet2 Resample2d (kernel_size=1) bilinear warp.
// input1: [B, C, H, W] float, input2 (flow): [B, 2, H, W] float
//
// Inner loop locked from R6 (proven optimum across 10 rounds: scalar
// gathers, 64x4 tile, unroll-4, 32 regs). Dead ends measured: vector
// gathers (pay sector bill per 4B slice), smem staging (LDS conflicts +
// instr bloat), lockstep barriers, 32x8 tiles, stcg, unroll-8 (occupancy),
// dual channel streams (ALU pressure).
// R11: each block processes TWO vertically adjacent 64x4 tiles (y0, y0+4).
// Their gather windows share ~7 of 11 rows, so tile 2's TL/BL sectors hit
// the L1 lines tile 1 just filled (R6 measured ~12% redundant L2 refills
// from cross-SM neighbors). Also halves per-block prologue overhead.

#define BB 8
#define CC 32
#define HH 512
#define WW 512
#define HWSZ (HH * WW)   // 2^18

__device__ __forceinline__ void do_tile(const float* __restrict__ in1,
                                        const float* __restrict__ flow,
                                        float* __restrict__ out,
                                        int b, int w, int h) {
    int hw = (h << 9) | w;

    const float* fl = flow + ((size_t)b << 19); // b * 2 * HWSZ
    float dx = __ldg(fl + hw);
    float dy = __ldg(fl + HWSZ + hw);

    float xf = (float)w + dx;
    float yf = (float)h + dy;
    float x0f = floorf(xf);
    float y0f = floorf(yf);
    float alpha = xf - x0f;   // unclamped fractional weights
    float beta  = yf - y0f;

    int ix0 = (int)x0f;
    int iy0 = (int)y0f;
    int xL = min(max(ix0,     0), WW - 1);
    int xR = min(max(ix0 + 1, 0), WW - 1);
    int yT = min(max(iy0,     0), HH - 1);
    int yB = min(max(iy0 + 1, 0), HH - 1);

    float wTR = alpha * (1.0f - beta);
    float wBL = (1.0f - alpha) * beta;
    float wBR = alpha * beta;
    float wTL = 1.0f - wTR - wBL - wBR;

    const float* base = in1 + ((size_t)b << 23);   // b * C * HWSZ
    const float* pTL = base + ((yT << 9) + xL);
    const float* pTR = base + ((yT << 9) + xR);
    const float* pBL = base + ((yB << 9) + xL);
    const float* pBR = base + ((yB << 9) + xR);
    float* op = out + ((size_t)b << 23) + hw;

    #pragma unroll 4
    for (int c = 0; c < CC; c++) {
        int off = c << 18;   // c * HWSZ
        float v = wTL * __ldg(pTL + off)
                + wTR * __ldg(pTR + off)
                + wBL * __ldg(pBL + off)
                + wBR * __ldg(pBR + off);
        op[off] = v;
    }
}

__global__ __launch_bounds__(256, 8)
void resample2d_kernel(const float* __restrict__ in1,
                       const float* __restrict__ flow,
                       float* __restrict__ out) {
    // Block = two stacked 64x4 tiles (64x8 region).
    // Grid = 8 x-chunks * 64 y-groups * 8 batches = 4096.
    int blk = blockIdx.x;
    int x0 = (blk & 7) << 6;            // x-chunk * 64
    int y0 = ((blk >> 3) & 63) << 3;    // y-group * 8
    int b  = blk >> 9;                  // batch

    int w = x0 + (threadIdx.x & 63);
    int h = y0 + (threadIdx.x >> 6);

    do_tile(in1, flow, out, b, w, h);        // rows [y0, y0+4)
    do_tile(in1, flow, out, b, w, h + 4);    // rows [y0+4, y0+8) — window
                                             // overlaps tile 1's in L1
}

extern "C" void kernel_launch(void* const* d_in, const int* in_sizes, int n_in,
                              void* d_out, int out_size) {
    const float* input1 = (const float*)d_in[0];
    const float* input2 = (const float*)d_in[1];
    float* out = (float*)d_out;

    const int blocks = 8 * 64 * BB;   // 4096 blocks, 64x8 region each
    resample2d_kernel<<<blocks, 256>>>(input1, input2, out);
}

// round 12
// speedup vs baseline: 1.1553x; 1.1553x over previous
#include <cuda_runtime.h>

// FlowNet2 Resample2d (kernel_size=1) bilinear warp — converged structure.
// input1: [B, C, H, W] float, input2 (flow): [B, 2, H, W] float
//
// Winning structure (R6, best of 11 measured variants): 64x4 pixel tiles,
// one thread per pixel, scalar gathers, channel loop unroll-4, 32 regs,
// 8 blocks/SM. The kernel is L1 sector-return bound (~14 L1 cyc per
// warp-channel: 4 gathers x ~3.65 sectors-of-return + 1 store wavefront).
// Measured dead ends: vector gathers (sector bill paid per 4B slice),
// smem staging (LDS conflicts + instr bloat), lockstep barriers, 32x8
// tiles, stcg stores, unroll-8 (occupancy loss), dual channel streams
// (issue pressure), sequential paired tiles (temporal locality loss).
// Final lever: request 0% smem carveout -> maximum unified L1 capacity,
// protecting the gather hit rate that keeps sector refills off L2.

#define BB 8
#define CC 32
#define HH 512
#define WW 512
#define HWSZ (HH * WW)   // 2^18

__global__ __launch_bounds__(256, 8)
void resample2d_kernel(const float* __restrict__ in1,
                       const float* __restrict__ flow,
                       float* __restrict__ out) {
    // Block tile: 64 px wide x 4 rows. Grid = 8 x-chunks * 128 y-chunks * 8 b.
    int blk = blockIdx.x;
    int x0 = (blk & 7) << 6;            // x-chunk * 64
    int y0 = ((blk >> 3) & 127) << 2;   // y-chunk * 4
    int b  = blk >> 10;                 // batch

    int w = x0 + (threadIdx.x & 63);
    int h = y0 + (threadIdx.x >> 6);
    int hw = (h << 9) | w;

    const float* fl = flow + ((size_t)b << 19); // b * 2 * HWSZ
    float dx = __ldg(fl + hw);
    float dy = __ldg(fl + HWSZ + hw);

    float xf = (float)w + dx;
    float yf = (float)h + dy;
    float x0f = floorf(xf);
    float y0f = floorf(yf);
    float alpha = xf - x0f;   // unclamped fractional weights
    float beta  = yf - y0f;

    int ix0 = (int)x0f;
    int iy0 = (int)y0f;
    int xL = min(max(ix0,     0), WW - 1);
    int xR = min(max(ix0 + 1, 0), WW - 1);
    int yT = min(max(iy0,     0), HH - 1);
    int yB = min(max(iy0 + 1, 0), HH - 1);

    float wTR = alpha * (1.0f - beta);
    float wBL = (1.0f - alpha) * beta;
    float wBR = alpha * beta;
    float wTL = 1.0f - wTR - wBL - wBR;

    const float* base = in1 + ((size_t)b << 23);   // b * C * HWSZ
    const float* pTL = base + ((yT << 9) + xL);
    const float* pTR = base + ((yT << 9) + xR);
    const float* pBL = base + ((yB << 9) + xL);
    const float* pBR = base + ((yB << 9) + xR);
    float* op = out + ((size_t)b << 23) + hw;

    #pragma unroll 4
    for (int c = 0; c < CC; c++) {
        int off = c << 18;   // c * HWSZ
        float v = wTL * __ldg(pTL + off)
                + wTR * __ldg(pTR + off)
                + wBL * __ldg(pBL + off)
                + wBR * __ldg(pBR + off);
        op[off] = v;
    }
}

extern "C" void kernel_launch(void* const* d_in, const int* in_sizes, int n_in,
                              void* d_out, int out_size) {
    const float* input1 = (const float*)d_in[0];
    const float* input2 = (const float*)d_in[1];
    float* out = (float*)d_out;

    // Max-L1 carveout (kernel uses no smem). Host-side attribute set: not a
    // stream op, not an allocation; executes at capture time, deterministic.
    cudaFuncSetAttribute(resample2d_kernel,
                         cudaFuncAttributePreferredSharedMemoryCarveout, 0);

    const int blocks = 8 * 128 * BB;   // 8192 tiles of 64x4
    resample2d_kernel<<<blocks, 256>>>(input1, input2, out);
}